// round 1
// baseline (speedup 1.0000x reference)
#include <cuda_runtime.h>
#include <math.h>

#define DMODEL 1024
#define NHEAD  16
#define DHEAD  64
#define SCTX   2048
#define NBATCH 2
#define MTOT   (NBATCH * SCTX)   // 4096

// Scratch (allocation-free rule: __device__ globals)
__device__ float g_q[(size_t)MTOT * DMODEL];
__device__ float g_k[(size_t)MTOT * DMODEL];
__device__ float g_v[(size_t)MTOT * DMODEL];
__device__ float g_z[(size_t)MTOT * DMODEL];
__device__ float g_invfreq[DHEAD / 2];

// ---------------------------------------------------------------------------
// RoPE inv_freq table (double precision, matches jnp within 1 ulp)
// ---------------------------------------------------------------------------
__global__ void rope_init_kernel() {
    int i = threadIdx.x;
    if (i < DHEAD / 2) {
        g_invfreq[i] = (float)(1.0 / pow(10000.0, (double)(2 * i) / (double)DHEAD));
    }
}

// ---------------------------------------------------------------------------
// Generic C[M,N] = A[M,K] @ W[N,K]^T (+bias[n]) (+resid[m,n])
// 64x64 tile, BK=16, 256 threads, 4x4 per thread, fp32.
// ---------------------------------------------------------------------------
__global__ void __launch_bounds__(256) gemm_kernel(
    const float* __restrict__ A, const float* __restrict__ W,
    const float* __restrict__ bias, const float* __restrict__ resid,
    float* __restrict__ C, int M, int N, int K)
{
    __shared__ float As[16][68];
    __shared__ float Bs[16][68];

    const int tid = threadIdx.x;
    const int tx = tid & 15;
    const int ty = tid >> 4;
    const int m0 = blockIdx.y << 6;
    const int n0 = blockIdx.x << 6;

    // load mapping: 64 rows x 4 float4 columns
    const int lr  = tid >> 2;          // 0..63
    const int lc4 = (tid & 3) << 2;    // 0,4,8,12

    const float* Ap = A + (size_t)(m0 + lr) * K + lc4;
    const float* Wp = W + (size_t)(n0 + lr) * K + lc4;

    float acc[4][4] = {};

    for (int k0 = 0; k0 < K; k0 += 16) {
        float4 av = *(const float4*)(Ap + k0);
        float4 wv = *(const float4*)(Wp + k0);
        __syncthreads();
        As[lc4 + 0][lr] = av.x;  As[lc4 + 1][lr] = av.y;
        As[lc4 + 2][lr] = av.z;  As[lc4 + 3][lr] = av.w;
        Bs[lc4 + 0][lr] = wv.x;  Bs[lc4 + 1][lr] = wv.y;
        Bs[lc4 + 2][lr] = wv.z;  Bs[lc4 + 3][lr] = wv.w;
        __syncthreads();
        #pragma unroll
        for (int k = 0; k < 16; k++) {
            float4 a = *(const float4*)&As[k][ty << 2];
            float4 b = *(const float4*)&Bs[k][tx << 2];
            float aa[4] = {a.x, a.y, a.z, a.w};
            float bb[4] = {b.x, b.y, b.z, b.w};
            #pragma unroll
            for (int u = 0; u < 4; u++)
                #pragma unroll
                for (int v = 0; v < 4; v++)
                    acc[u][v] = fmaf(aa[u], bb[v], acc[u][v]);
        }
    }

    #pragma unroll
    for (int u = 0; u < 4; u++) {
        const int m = m0 + (ty << 2) + u;
        const int n = n0 + (tx << 2);
        float4 r = make_float4(acc[u][0], acc[u][1], acc[u][2], acc[u][3]);
        if (bias) {
            float4 bv = *(const float4*)(bias + n);
            r.x += bv.x; r.y += bv.y; r.z += bv.z; r.w += bv.w;
        }
        if (resid) {
            float4 xv = *(const float4*)(resid + (size_t)m * N + n);
            r.x += xv.x; r.y += xv.y; r.z += xv.z; r.w += xv.w;
        }
        *(float4*)(C + (size_t)m * N + n) = r;
    }
}

// ---------------------------------------------------------------------------
// RMSNorm (per head, D=64) + RoPE, in place on q and k.
// One warp per (b,s,h) row; lane handles the rope pair (2*lane, 2*lane+1).
// ---------------------------------------------------------------------------
__global__ void __launch_bounds__(256) norm_rope_kernel(
    float* __restrict__ q, float* __restrict__ k, const float* __restrict__ w)
{
    const int warp = threadIdx.x >> 5;
    const int lane = threadIdx.x & 31;
    const int row = blockIdx.x * 8 + warp;     // 0..65535 = (b*S+s)*16 + h
    float* base = (blockIdx.y == 0) ? q : k;
    const int bs = row >> 4;                   // b*S + s
    const int s  = bs & (SCTX - 1);
    float* p = base + (size_t)bs * DMODEL + (row & 15) * DHEAD;

    const int d0 = lane * 2;
    float e = p[d0];
    float o = p[d0 + 1];

    float ss = e * e + o * o;
    #pragma unroll
    for (int m = 16; m; m >>= 1) ss += __shfl_xor_sync(0xffffffffu, ss, m);

    const float r = rsqrtf(ss * (1.0f / (float)DHEAD) + 1.1920928955078125e-07f);
    const float en = e * r * w[d0];
    const float on = o * r * w[d0 + 1];

    // emb = concat([freqs, freqs]): angle(j) = s * invfreq[j < 32 ? j : j-32]
    const int i0 = (d0 < 32) ? d0 : d0 - 32;
    const int i1 = (d0 + 1 < 32) ? (d0 + 1) : (d0 + 1 - 32);
    const float a0 = (float)s * g_invfreq[i0];
    const float a1 = (float)s * g_invfreq[i1];
    float c0, s0, c1, s1;
    sincosf(a0, &s0, &c0);
    sincosf(a1, &s1, &c1);

    p[d0]     = en * c0 - on * s0;   // x_rot[2i]   = -x[2i+1]
    p[d0 + 1] = on * c1 + en * s1;   // x_rot[2i+1] =  x[2i]
}

// ---------------------------------------------------------------------------
// Fused quadratic attention:
//   z[b,i,h,:] = sum_{j<=i} (q[i]·k[j] / 64)^2 * v[j]
// Grid: (q_tile 0..31, b*h 0..31). Block 256 threads, BQ=BK=64, D=64.
// Smem: Qs[64][64], KsT[64][64] (union with Ps), Vs[64][64]  => 48 KB static.
// ---------------------------------------------------------------------------
__global__ void __launch_bounds__(256) attn_kernel(
    const float* __restrict__ q, const float* __restrict__ k,
    const float* __restrict__ v, float* __restrict__ z)
{
    __shared__ float Qs[64 * 64];    // [i][d]
    __shared__ float KPs[64 * 64];   // phase 1: KsT [d][j]; phase 2: Ps [i][j]
    __shared__ float Vs[64 * 64];    // [j][d]

    const int tid = threadIdx.x;
    const int tx = tid & 15;
    const int ty = tid >> 4;
    const int qt = blockIdx.x;
    const int bh = blockIdx.y;
    const int b = bh >> 4;
    const int h = bh & 15;
    const size_t base = (size_t)b * SCTX * DMODEL + (size_t)h * DHEAD;

    // Load Q tile (coalesced float4)
    #pragma unroll
    for (int it = 0; it < 4; it++) {
        const int idx = tid + it * 256;
        const int row = idx >> 4;
        const int c4  = (idx & 15) << 2;
        float4 qv = *(const float4*)&q[base + (size_t)((qt << 6) + row) * DMODEL + c4];
        *(float4*)&Qs[row * 64 + c4] = qv;
    }

    float zacc[4][4] = {};
    const float inv_d = 1.0f / (float)DHEAD;

    for (int kt = 0; kt <= qt; kt++) {
        __syncthreads();   // previous iteration's reads of KPs/Vs done

        // Load K (transposed into KsT[d][j]) and V tiles
        #pragma unroll
        for (int it = 0; it < 4; it++) {
            const int idx = tid + it * 256;
            const int row = idx >> 4;          // j within tile
            const int c4  = (idx & 15) << 2;   // d base
            const size_t goff = base + (size_t)((kt << 6) + row) * DMODEL + c4;
            float4 kv = *(const float4*)&k[goff];
            float4 vv = *(const float4*)&v[goff];
            KPs[(c4 + 0) * 64 + row] = kv.x;
            KPs[(c4 + 1) * 64 + row] = kv.y;
            KPs[(c4 + 2) * 64 + row] = kv.z;
            KPs[(c4 + 3) * 64 + row] = kv.w;
            *(float4*)&Vs[row * 64 + c4] = vv;
        }
        __syncthreads();

        // S = Q @ K^T (64x64), 4x4 per thread
        float sacc[4][4] = {};
        #pragma unroll 8
        for (int d = 0; d < 64; d++) {
            float a0 = Qs[((ty << 2) + 0) * 64 + d];
            float a1 = Qs[((ty << 2) + 1) * 64 + d];
            float a2 = Qs[((ty << 2) + 2) * 64 + d];
            float a3 = Qs[((ty << 2) + 3) * 64 + d];
            float4 bv = *(const float4*)&KPs[d * 64 + (tx << 2)];
            float bb[4] = {bv.x, bv.y, bv.z, bv.w};
            #pragma unroll
            for (int vv2 = 0; vv2 < 4; vv2++) {
                sacc[0][vv2] = fmaf(a0, bb[vv2], sacc[0][vv2]);
                sacc[1][vv2] = fmaf(a1, bb[vv2], sacc[1][vv2]);
                sacc[2][vv2] = fmaf(a2, bb[vv2], sacc[2][vv2]);
                sacc[3][vv2] = fmaf(a3, bb[vv2], sacc[3][vv2]);
            }
        }

        __syncthreads();   // all reads of KsT done before overwriting with Ps

        // pattern = (S/64)^2, causal mask on the diagonal tile
        #pragma unroll
        for (int u = 0; u < 4; u++) {
            float4 pr;
            float* pp = (float*)&pr;
            #pragma unroll
            for (int vv2 = 0; vv2 < 4; vv2++) {
                float sv = sacc[u][vv2] * inv_d;
                sv *= sv;
                if (kt == qt) {
                    const int il = (ty << 2) + u;
                    const int jl = (tx << 2) + vv2;
                    if (jl > il) sv = 0.0f;
                }
                pp[vv2] = sv;
            }
            *(float4*)&KPs[((ty << 2) + u) * 64 + (tx << 2)] = pr;
        }
        __syncthreads();

        // Z += P @ V
        #pragma unroll 8
        for (int j = 0; j < 64; j++) {
            float p0 = KPs[((ty << 2) + 0) * 64 + j];
            float p1 = KPs[((ty << 2) + 1) * 64 + j];
            float p2 = KPs[((ty << 2) + 2) * 64 + j];
            float p3 = KPs[((ty << 2) + 3) * 64 + j];
            float4 vv4 = *(const float4*)&Vs[j * 64 + (tx << 2)];
            float vb[4] = {vv4.x, vv4.y, vv4.z, vv4.w};
            #pragma unroll
            for (int vv2 = 0; vv2 < 4; vv2++) {
                zacc[0][vv2] = fmaf(p0, vb[vv2], zacc[0][vv2]);
                zacc[1][vv2] = fmaf(p1, vb[vv2], zacc[1][vv2]);
                zacc[2][vv2] = fmaf(p2, vb[vv2], zacc[2][vv2]);
                zacc[3][vv2] = fmaf(p3, vb[vv2], zacc[3][vv2]);
            }
        }
    }

    // Write Z tile
    #pragma unroll
    for (int u = 0; u < 4; u++) {
        const int i = (qt << 6) + (ty << 2) + u;
        float4 r = make_float4(zacc[u][0], zacc[u][1], zacc[u][2], zacc[u][3]);
        *(float4*)&z[base + (size_t)i * DMODEL + (tx << 2)] = r;
    }
}

// ---------------------------------------------------------------------------
extern "C" void kernel_launch(void* const* d_in, const int* in_sizes, int n_in,
                              void* d_out, int out_size)
{
    const float* x  = (const float*)d_in[0];
    const float* Wq = (const float*)d_in[1];
    const float* bq = (const float*)d_in[2];
    const float* Wk = (const float*)d_in[3];
    const float* bk = (const float*)d_in[4];
    const float* Wv = (const float*)d_in[5];
    const float* bv = (const float*)d_in[6];
    const float* Wo = (const float*)d_in[7];
    const float* nw = (const float*)d_in[8];
    float* out = (float*)d_out;

    float *q, *k, *v, *z;
    cudaGetSymbolAddress((void**)&q, g_q);
    cudaGetSymbolAddress((void**)&k, g_k);
    cudaGetSymbolAddress((void**)&v, g_v);
    cudaGetSymbolAddress((void**)&z, g_z);

    rope_init_kernel<<<1, 32>>>();

    dim3 ggrid(DMODEL / 64, MTOT / 64);   // (16, 64)
    gemm_kernel<<<ggrid, 256>>>(x, Wq, bq, nullptr, q, MTOT, DMODEL, DMODEL);
    gemm_kernel<<<ggrid, 256>>>(x, Wk, bk, nullptr, k, MTOT, DMODEL, DMODEL);
    gemm_kernel<<<ggrid, 256>>>(x, Wv, bv, nullptr, v, MTOT, DMODEL, DMODEL);

    norm_rope_kernel<<<dim3(MTOT * NHEAD / 8, 2), 256>>>(q, k, nw);

    attn_kernel<<<dim3(SCTX / 64, NBATCH * NHEAD), 256>>>(q, k, v, z);

    gemm_kernel<<<ggrid, 256>>>(z, Wo, nullptr, x, out, MTOT, DMODEL, DMODEL);
}

// round 5
// speedup vs baseline: 1.2843x; 1.2843x over previous
#include <cuda_runtime.h>
#include <math.h>
#include <stdint.h>

#define DMODEL 1024
#define NHEAD  16
#define DHEAD  64
#define SCTX   2048
#define NBATCH 2
#define MTOT   (NBATCH * SCTX)   // 4096

// Scratch (allocation-free rule: __device__ globals)
__device__ float g_q[(size_t)MTOT * DMODEL];
__device__ float g_k[(size_t)MTOT * DMODEL];
__device__ float g_v[(size_t)MTOT * DMODEL];
__device__ float g_z[(size_t)MTOT * DMODEL];
__device__ float g_invfreq[DHEAD / 2];

// ---------------------------------------------------------------------------
// helpers
// ---------------------------------------------------------------------------
__device__ __forceinline__ float f2tf32(float a) {
    uint32_t r;
    asm("cvt.rna.tf32.f32 %0, %1;" : "=r"(r) : "f"(a));
    return __uint_as_float(r);
}

__device__ __forceinline__ void mma_tf32(float* c, const uint32_t* a, const uint32_t* b) {
    asm volatile(
        "mma.sync.aligned.m16n8k8.row.col.f32.tf32.tf32.f32 "
        "{%0,%1,%2,%3}, {%4,%5,%6,%7}, {%8,%9}, {%0,%1,%2,%3};"
        : "+f"(c[0]), "+f"(c[1]), "+f"(c[2]), "+f"(c[3])
        : "r"(a[0]), "r"(a[1]), "r"(a[2]), "r"(a[3]), "r"(b[0]), "r"(b[1]));
}

// ---------------------------------------------------------------------------
// RoPE inv_freq table
// ---------------------------------------------------------------------------
__global__ void rope_init_kernel() {
    int i = threadIdx.x;
    if (i < DHEAD / 2) {
        g_invfreq[i] = (float)(1.0 / pow(10000.0, (double)(2 * i) / (double)DHEAD));
    }
}

// ---------------------------------------------------------------------------
// Tensor-core (mma.sync tf32, 3xTF32-compensated) GEMM:
//   C[4096,1024] = A[4096,1024] @ W[1024,1024]^T (+bias) (+resid)
// CTA 128x128, 256 threads (8 warps, each 32x64), K-chunk 32.
// Smem: Ahi/Alo/Bhi/Blo each [128][36] floats (stride 36 -> conflict-free
// fragment loads: bank = 4*row + k).
// ---------------------------------------------------------------------------
#define GSTRIDE 36
#define GTILEF  (128 * GSTRIDE)              // floats per sub-tile
#define GSMEM_TOTAL (4 * GTILEF * 4)         // 73728 bytes

__global__ void __launch_bounds__(256) gemm_tc(
    const float* __restrict__ A, const float* __restrict__ W,
    const float* __restrict__ bias, const float* __restrict__ resid,
    float* __restrict__ C)
{
    extern __shared__ float sm[];
    float* Ah = sm;
    float* Al = sm + GTILEF;
    float* Bh = sm + 2 * GTILEF;
    float* Bl = sm + 3 * GTILEF;

    const int tid  = threadIdx.x;
    const int wid  = tid >> 5;
    const int lane = tid & 31;
    const int gid  = lane >> 2;      // 0..7
    const int tig  = lane & 3;       // 0..3
    const int warpM = wid & 3;       // m offset 32*warpM
    const int warpN = wid >> 2;      // n offset 64*warpN
    const int m0 = blockIdx.y * 128;
    const int n0 = blockIdx.x * 128;

    // global loader mapping: 1024 float4 per matrix per chunk, 4 per thread
    // idx = tid + 256*i : row = idx>>3 (0..127), c4 = (idx&7)*4
    const int lrow = tid >> 3;            // base row for i=0 (rows advance by 32)
    const int lc4  = (tid & 7) << 2;

    const float* Ap = A + (size_t)(m0 + lrow) * DMODEL + lc4;
    const float* Wp = W + (size_t)(n0 + lrow) * DMODEL + lc4;

    float4 ra[4], rb[4];
    #pragma unroll
    for (int i = 0; i < 4; i++) {
        ra[i] = *(const float4*)(Ap + (size_t)i * 32 * DMODEL);
        rb[i] = *(const float4*)(Wp + (size_t)i * 32 * DMODEL);
    }

    float acc[2][8][4];
    #pragma unroll
    for (int mt = 0; mt < 2; mt++)
        #pragma unroll
        for (int nt = 0; nt < 8; nt++)
            #pragma unroll
            for (int r = 0; r < 4; r++) acc[mt][nt][r] = 0.0f;

    for (int c = 0; c < DMODEL / 32; c++) {
        if (c > 0) __syncthreads();   // previous compute done reading smem

        #pragma unroll
        for (int i = 0; i < 4; i++) {
            const int srow = lrow + 32 * i;
            float4 a = ra[i], b = rb[i];
            float4 ah, al, bh, bl;
            ah.x = f2tf32(a.x); al.x = f2tf32(a.x - ah.x);
            ah.y = f2tf32(a.y); al.y = f2tf32(a.y - ah.y);
            ah.z = f2tf32(a.z); al.z = f2tf32(a.z - ah.z);
            ah.w = f2tf32(a.w); al.w = f2tf32(a.w - ah.w);
            bh.x = f2tf32(b.x); bl.x = f2tf32(b.x - bh.x);
            bh.y = f2tf32(b.y); bl.y = f2tf32(b.y - bh.y);
            bh.z = f2tf32(b.z); bl.z = f2tf32(b.z - bh.z);
            bh.w = f2tf32(b.w); bl.w = f2tf32(b.w - bh.w);
            *(float4*)&Ah[srow * GSTRIDE + lc4] = ah;
            *(float4*)&Al[srow * GSTRIDE + lc4] = al;
            *(float4*)&Bh[srow * GSTRIDE + lc4] = bh;
            *(float4*)&Bl[srow * GSTRIDE + lc4] = bl;
        }

        if (c + 1 < DMODEL / 32) {
            #pragma unroll
            for (int i = 0; i < 4; i++) {
                ra[i] = *(const float4*)(Ap + (c + 1) * 32 + (size_t)i * 32 * DMODEL);
                rb[i] = *(const float4*)(Wp + (c + 1) * 32 + (size_t)i * 32 * DMODEL);
            }
        }
        __syncthreads();

        #pragma unroll
        for (int kk = 0; kk < 4; kk++) {
            const int ko = kk * 8 + tig;
            uint32_t afh[2][4], afl[2][4], bfh[8][2], bfl[8][2];
            #pragma unroll
            for (int mt = 0; mt < 2; mt++) {
                const int base = (warpM * 32 + mt * 16 + gid) * GSTRIDE + ko;
                afh[mt][0] = __float_as_uint(Ah[base]);
                afh[mt][1] = __float_as_uint(Ah[base + 8 * GSTRIDE]);
                afh[mt][2] = __float_as_uint(Ah[base + 4]);
                afh[mt][3] = __float_as_uint(Ah[base + 8 * GSTRIDE + 4]);
                afl[mt][0] = __float_as_uint(Al[base]);
                afl[mt][1] = __float_as_uint(Al[base + 8 * GSTRIDE]);
                afl[mt][2] = __float_as_uint(Al[base + 4]);
                afl[mt][3] = __float_as_uint(Al[base + 8 * GSTRIDE + 4]);
            }
            #pragma unroll
            for (int nt = 0; nt < 8; nt++) {
                const int base = (warpN * 64 + nt * 8 + gid) * GSTRIDE + ko;
                bfh[nt][0] = __float_as_uint(Bh[base]);
                bfh[nt][1] = __float_as_uint(Bh[base + 4]);
                bfl[nt][0] = __float_as_uint(Bl[base]);
                bfl[nt][1] = __float_as_uint(Bl[base + 4]);
            }
            #pragma unroll
            for (int mt = 0; mt < 2; mt++)
                #pragma unroll
                for (int nt = 0; nt < 8; nt++) {
                    mma_tf32(acc[mt][nt], afh[mt], bfh[nt]);
                    mma_tf32(acc[mt][nt], afh[mt], bfl[nt]);
                    mma_tf32(acc[mt][nt], afl[mt], bfh[nt]);
                }
        }
    }

    // epilogue
    #pragma unroll
    for (int mt = 0; mt < 2; mt++) {
        #pragma unroll
        for (int nt = 0; nt < 8; nt++) {
            const int m = m0 + warpM * 32 + mt * 16 + gid;
            const int n = n0 + warpN * 64 + nt * 8 + 2 * tig;
            float2 r0 = make_float2(acc[mt][nt][0], acc[mt][nt][1]);
            float2 r1 = make_float2(acc[mt][nt][2], acc[mt][nt][3]);
            if (bias) {
                float b0 = __ldg(&bias[n]);
                float b1 = __ldg(&bias[n + 1]);
                r0.x += b0; r0.y += b1;
                r1.x += b0; r1.y += b1;
            }
            if (resid) {
                float2 x0 = *(const float2*)&resid[(size_t)m * DMODEL + n];
                float2 x1 = *(const float2*)&resid[(size_t)(m + 8) * DMODEL + n];
                r0.x += x0.x; r0.y += x0.y;
                r1.x += x1.x; r1.y += x1.y;
            }
            *(float2*)&C[(size_t)m * DMODEL + n] = r0;
            *(float2*)&C[(size_t)(m + 8) * DMODEL + n] = r1;
        }
    }
}

// ---------------------------------------------------------------------------
// RMSNorm (per head, D=64) + RoPE, in place on q and k.
// ---------------------------------------------------------------------------
__global__ void __launch_bounds__(256) norm_rope_kernel(
    float* __restrict__ q, float* __restrict__ k, const float* __restrict__ w)
{
    const int warp = threadIdx.x >> 5;
    const int lane = threadIdx.x & 31;
    const int row = blockIdx.x * 8 + warp;
    float* base = (blockIdx.y == 0) ? q : k;
    const int bs = row >> 4;
    const int s  = bs & (SCTX - 1);
    float* p = base + (size_t)bs * DMODEL + (row & 15) * DHEAD;

    const int d0 = lane * 2;
    float e = p[d0];
    float o = p[d0 + 1];

    float ss = e * e + o * o;
    #pragma unroll
    for (int m = 16; m; m >>= 1) ss += __shfl_xor_sync(0xffffffffu, ss, m);

    const float r = rsqrtf(ss * (1.0f / (float)DHEAD) + 1.1920928955078125e-07f);
    const float en = e * r * w[d0];
    const float on = o * r * w[d0 + 1];

    const int i0 = (d0 < 32) ? d0 : d0 - 32;
    const int i1 = (d0 + 1 < 32) ? (d0 + 1) : (d0 + 1 - 32);
    const float a0 = (float)s * g_invfreq[i0];
    const float a1 = (float)s * g_invfreq[i1];
    float c0, s0, c1, s1;
    sincosf(a0, &s0, &c0);
    sincosf(a1, &s1, &c1);

    p[d0]     = en * c0 - on * s0;
    p[d0 + 1] = on * c1 + en * s1;
}

// ---------------------------------------------------------------------------
// Fused quadratic attention (SIMT fp32)
// ---------------------------------------------------------------------------
__global__ void __launch_bounds__(256) attn_kernel(
    const float* __restrict__ q, const float* __restrict__ k,
    const float* __restrict__ v, float* __restrict__ z)
{
    __shared__ float Qs[64 * 64];
    __shared__ float KPs[64 * 64];
    __shared__ float Vs[64 * 64];

    const int tid = threadIdx.x;
    const int tx = tid & 15;
    const int ty = tid >> 4;
    const int qt = blockIdx.x;
    const int bh = blockIdx.y;
    const int b = bh >> 4;
    const int h = bh & 15;
    const size_t base = (size_t)b * SCTX * DMODEL + (size_t)h * DHEAD;

    #pragma unroll
    for (int it = 0; it < 4; it++) {
        const int idx = tid + it * 256;
        const int row = idx >> 4;
        const int c4  = (idx & 15) << 2;
        float4 qv = *(const float4*)&q[base + (size_t)((qt << 6) + row) * DMODEL + c4];
        *(float4*)&Qs[row * 64 + c4] = qv;
    }

    float zacc[4][4] = {};
    const float inv_d = 1.0f / (float)DHEAD;

    for (int kt = 0; kt <= qt; kt++) {
        __syncthreads();

        #pragma unroll
        for (int it = 0; it < 4; it++) {
            const int idx = tid + it * 256;
            const int row = idx >> 4;
            const int c4  = (idx & 15) << 2;
            const size_t goff = base + (size_t)((kt << 6) + row) * DMODEL + c4;
            float4 kv = *(const float4*)&k[goff];
            float4 vv = *(const float4*)&v[goff];
            KPs[(c4 + 0) * 64 + row] = kv.x;
            KPs[(c4 + 1) * 64 + row] = kv.y;
            KPs[(c4 + 2) * 64 + row] = kv.z;
            KPs[(c4 + 3) * 64 + row] = kv.w;
            *(float4*)&Vs[row * 64 + c4] = vv;
        }
        __syncthreads();

        float sacc[4][4] = {};
        #pragma unroll 8
        for (int d = 0; d < 64; d++) {
            float a0 = Qs[((ty << 2) + 0) * 64 + d];
            float a1 = Qs[((ty << 2) + 1) * 64 + d];
            float a2 = Qs[((ty << 2) + 2) * 64 + d];
            float a3 = Qs[((ty << 2) + 3) * 64 + d];
            float4 bv = *(const float4*)&KPs[d * 64 + (tx << 2)];
            float bb[4] = {bv.x, bv.y, bv.z, bv.w};
            #pragma unroll
            for (int vv2 = 0; vv2 < 4; vv2++) {
                sacc[0][vv2] = fmaf(a0, bb[vv2], sacc[0][vv2]);
                sacc[1][vv2] = fmaf(a1, bb[vv2], sacc[1][vv2]);
                sacc[2][vv2] = fmaf(a2, bb[vv2], sacc[2][vv2]);
                sacc[3][vv2] = fmaf(a3, bb[vv2], sacc[3][vv2]);
            }
        }

        __syncthreads();

        #pragma unroll
        for (int u = 0; u < 4; u++) {
            float4 pr;
            float* pp = (float*)&pr;
            #pragma unroll
            for (int vv2 = 0; vv2 < 4; vv2++) {
                float sv = sacc[u][vv2] * inv_d;
                sv *= sv;
                if (kt == qt) {
                    const int il = (ty << 2) + u;
                    const int jl = (tx << 2) + vv2;
                    if (jl > il) sv = 0.0f;
                }
                pp[vv2] = sv;
            }
            *(float4*)&KPs[((ty << 2) + u) * 64 + (tx << 2)] = pr;
        }
        __syncthreads();

        #pragma unroll 8
        for (int j = 0; j < 64; j++) {
            float p0 = KPs[((ty << 2) + 0) * 64 + j];
            float p1 = KPs[((ty << 2) + 1) * 64 + j];
            float p2 = KPs[((ty << 2) + 2) * 64 + j];
            float p3 = KPs[((ty << 2) + 3) * 64 + j];
            float4 vv4 = *(const float4*)&Vs[j * 64 + (tx << 2)];
            float vb[4] = {vv4.x, vv4.y, vv4.z, vv4.w};
            #pragma unroll
            for (int vv2 = 0; vv2 < 4; vv2++) {
                zacc[0][vv2] = fmaf(p0, vb[vv2], zacc[0][vv2]);
                zacc[1][vv2] = fmaf(p1, vb[vv2], zacc[1][vv2]);
                zacc[2][vv2] = fmaf(p2, vb[vv2], zacc[2][vv2]);
                zacc[3][vv2] = fmaf(p3, vb[vv2], zacc[3][vv2]);
            }
        }
    }

    #pragma unroll
    for (int u = 0; u < 4; u++) {
        const int i = (qt << 6) + (ty << 2) + u;
        float4 r = make_float4(zacc[u][0], zacc[u][1], zacc[u][2], zacc[u][3]);
        *(float4*)&z[base + (size_t)i * DMODEL + (tx << 2)] = r;
    }
}

// ---------------------------------------------------------------------------
extern "C" void kernel_launch(void* const* d_in, const int* in_sizes, int n_in,
                              void* d_out, int out_size)
{
    const float* x  = (const float*)d_in[0];
    const float* Wq = (const float*)d_in[1];
    const float* bq = (const float*)d_in[2];
    const float* Wk = (const float*)d_in[3];
    const float* bk = (const float*)d_in[4];
    const float* Wv = (const float*)d_in[5];
    const float* bv = (const float*)d_in[6];
    const float* Wo = (const float*)d_in[7];
    const float* nw = (const float*)d_in[8];
    float* out = (float*)d_out;

    float *q, *k, *v, *z;
    cudaGetSymbolAddress((void**)&q, g_q);
    cudaGetSymbolAddress((void**)&k, g_k);
    cudaGetSymbolAddress((void**)&v, g_v);
    cudaGetSymbolAddress((void**)&z, g_z);

    cudaFuncSetAttribute(gemm_tc, cudaFuncAttributeMaxDynamicSharedMemorySize,
                         GSMEM_TOTAL);

    rope_init_kernel<<<1, 32>>>();

    dim3 ggrid(DMODEL / 128, MTOT / 128);   // (8, 32)
    gemm_tc<<<ggrid, 256, GSMEM_TOTAL>>>(x, Wq, bq, nullptr, q);
    gemm_tc<<<ggrid, 256, GSMEM_TOTAL>>>(x, Wk, bk, nullptr, k);
    gemm_tc<<<ggrid, 256, GSMEM_TOTAL>>>(x, Wv, bv, nullptr, v);

    norm_rope_kernel<<<dim3(MTOT * NHEAD / 8, 2), 256>>>(q, k, nw);

    attn_kernel<<<dim3(SCTX / 64, NBATCH * NHEAD), 256>>>(q, k, v, z);

    gemm_tc<<<ggrid, 256, GSMEM_TOTAL>>>(z, Wo, nullptr, x, out);
}